// round 11
// baseline (speedup 1.0000x reference)
#include <cuda_runtime.h>
#include <math.h>

// ---------------------------------------------------------------------------
// Problem constants (fixed shapes)
// ---------------------------------------------------------------------------
#define Bc   4
#define Hc   8
#define SQc  2048
#define SKc  512
#define DMc  4096
#define DKc  512

// ---------------------------------------------------------------------------
// Scratch (device globals — allocation-free kernel_launch).
// buf1: q [b,h,sq,dk]  -> later im_attn [b,h,sq,dk]      (33.5M floats)
// buf2: p_attn [b,h,sq,sk] -> later x [b,sq,h*dk]        (33.5M floats)
// ---------------------------------------------------------------------------
__device__ float g_buf1[(size_t)Bc * Hc * SQc * DKc];
__device__ float g_buf2[(size_t)Bc * Hc * SQc * SKc];
__device__ float g_k   [(size_t)Bc * Hc * SKc * DKc];   // k  [b,h,sk,dk]
__device__ float g_vt  [(size_t)Bc * Hc * DKc * SKc];   // v^T [b,h,dk,sk]
__device__ float g_imft[(size_t)Bc * Hc * DKc * SKc];   // imf^T [b,h,dk,sk]

// ---------------------------------------------------------------------------
// SGEMM (NT: C[m,n] = sum_k A[m,k] * B[n,k]), fp32, 128x128x16 tile,
// 256 threads, 8x8 per thread (split 4+4 for conflict-free LDS.128).
// MODE 0: plain row-major + bias                  (output projection)
// MODE 1: split-head [b,h,s,dk] + bias            (q, k projections)
// MODE 2: split-head transposed [b,h,dk,s] + bias (v, imf projections)
// MODE 3: batched plain (z = b*H+h), * scale      (scores / p@imf)
// MODE 4: batched merge-head [b,sq,h*dk]          (im_attn @ v)
// ---------------------------------------------------------------------------
#define BM 128
#define BN 128
#define BK 16
#define PAD 4

template <int MODE, int S>
__global__ void __launch_bounds__(256, 2)
gemm_nt(const float* __restrict__ A, const float* __restrict__ Bm,
        const float* __restrict__ bias, float* __restrict__ C,
        int M, int N, int K,
        long long sA, long long sB, long long sC, float scale)
{
    __shared__ float As[BK][BM + PAD];
    __shared__ float Bs[BK][BN + PAD];

    const int tid = threadIdx.x;
    const int tx  = tid & 15;   // 0..15  (N dir)
    const int ty  = tid >> 4;   // 0..15  (M dir)
    const int m0  = blockIdx.y * BM;
    const int n0  = blockIdx.x * BN;

    const float* Ab = A  + (long long)blockIdx.z * sA;
    const float* Bb = Bm + (long long)blockIdx.z * sB;

    const int lrow = tid >> 2;        // 0..63
    const int lcol = (tid & 3) << 2;  // 0,4,8,12

    float acc[8][8];
#pragma unroll
    for (int i = 0; i < 8; i++)
#pragma unroll
        for (int j = 0; j < 8; j++) acc[i][j] = 0.f;

    for (int k0 = 0; k0 < K; k0 += BK) {
#pragma unroll
        for (int t = 0; t < 2; t++) {
            const int r = lrow + t * 64;
            float4 av = *(const float4*)(Ab + (long long)(m0 + r) * K + k0 + lcol);
            As[lcol + 0][r] = av.x; As[lcol + 1][r] = av.y;
            As[lcol + 2][r] = av.z; As[lcol + 3][r] = av.w;
            float4 bv = *(const float4*)(Bb + (long long)(n0 + r) * K + k0 + lcol);
            Bs[lcol + 0][r] = bv.x; Bs[lcol + 1][r] = bv.y;
            Bs[lcol + 2][r] = bv.z; Bs[lcol + 3][r] = bv.w;
        }
        __syncthreads();

#pragma unroll
        for (int kk = 0; kk < BK; kk++) {
            float a[8], b[8];
            float4 a0 = *(const float4*)&As[kk][ty * 4];
            float4 a1 = *(const float4*)&As[kk][64 + ty * 4];
            a[0] = a0.x; a[1] = a0.y; a[2] = a0.z; a[3] = a0.w;
            a[4] = a1.x; a[5] = a1.y; a[6] = a1.z; a[7] = a1.w;
            float4 b0v = *(const float4*)&Bs[kk][tx * 4];
            float4 b1v = *(const float4*)&Bs[kk][64 + tx * 4];
            b[0] = b0v.x; b[1] = b0v.y; b[2] = b0v.z; b[3] = b0v.w;
            b[4] = b1v.x; b[5] = b1v.y; b[6] = b1v.z; b[7] = b1v.w;
#pragma unroll
            for (int i = 0; i < 8; i++)
#pragma unroll
                for (int j = 0; j < 8; j++)
                    acc[i][j] = fmaf(a[i], b[j], acc[i][j]);
        }
        __syncthreads();
    }

    // --- epilogue: per-thread 8x8, split 4+4 row/col mapping ---
    int rows[8], cols[8];
#pragma unroll
    for (int i = 0; i < 4; i++) {
        rows[i]     = m0 + ty * 4 + i;
        rows[i + 4] = m0 + 64 + ty * 4 + i;
        cols[i]     = n0 + tx * 4 + i;
        cols[i + 4] = n0 + 64 + tx * 4 + i;
    }

    if (MODE == 0) {
#pragma unroll
        for (int i = 0; i < 8; i++) {
            const long long ro = (long long)rows[i] * N;
#pragma unroll
            for (int j = 0; j < 8; j++)
                C[ro + cols[j]] = acc[i][j] + bias[cols[j]];
        }
    } else if (MODE == 1) {
#pragma unroll
        for (int i = 0; i < 8; i++) {
            const int r = rows[i];
            const int bb = r / S, s = r % S;
#pragma unroll
            for (int j = 0; j < 8; j++) {
                const int c = cols[j];
                const int h = c >> 9, dk = c & 511;
                C[(((long long)(bb * Hc + h) * S + s) << 9) + dk] = acc[i][j] + bias[c];
            }
        }
    } else if (MODE == 2) {
#pragma unroll
        for (int i = 0; i < 8; i++) {
            const int r = rows[i];
            const int bb = r / S, s = r % S;
#pragma unroll
            for (int j = 0; j < 8; j++) {
                const int c = cols[j];
                const int h = c >> 9, dk = c & 511;
                C[((long long)(bb * Hc + h) * DKc + dk) * S + s] = acc[i][j] + bias[c];
            }
        }
    } else if (MODE == 3) {
        float* Cb = C + (long long)blockIdx.z * sC;
#pragma unroll
        for (int i = 0; i < 8; i++) {
            const long long ro = (long long)rows[i] * N;
#pragma unroll
            for (int j = 0; j < 8; j++)
                Cb[ro + cols[j]] = acc[i][j] * scale;
        }
    } else {  // MODE 4: merge heads -> [b, sq, h*dk]
        const int z = blockIdx.z;
        const int bb = z >> 3, h = z & 7;
#pragma unroll
        for (int i = 0; i < 8; i++) {
            const long long ro = ((long long)(bb * SQc + rows[i])) * DMc + h * DKc;
#pragma unroll
            for (int j = 0; j < 8; j++)
                C[ro + cols[j]] = acc[i][j];
        }
    }
}

// ---------------------------------------------------------------------------
// Row softmax, row length 512. One warp per row, 16 elems/lane in registers.
// ---------------------------------------------------------------------------
__global__ void softmax512(float* __restrict__ data, int nrows)
{
    const int warp = (blockIdx.x * blockDim.x + threadIdx.x) >> 5;
    const int lane = threadIdx.x & 31;
    if (warp >= nrows) return;
    float* row = data + (long long)warp * 512;

    float v[16];
    float mx = -3.4e38f;
#pragma unroll
    for (int i = 0; i < 16; i++) {
        v[i] = row[lane + i * 32];
        mx = fmaxf(mx, v[i]);
    }
#pragma unroll
    for (int o = 16; o > 0; o >>= 1)
        mx = fmaxf(mx, __shfl_xor_sync(0xffffffffu, mx, o));

    float sum = 0.f;
#pragma unroll
    for (int i = 0; i < 16; i++) {
        v[i] = __expf(v[i] - mx);
        sum += v[i];
    }
#pragma unroll
    for (int o = 16; o > 0; o >>= 1)
        sum += __shfl_xor_sync(0xffffffffu, sum, o);

    const float inv = 1.0f / sum;
#pragma unroll
    for (int i = 0; i < 16; i++)
        row[lane + i * 32] = v[i] * inv;
}

// ---------------------------------------------------------------------------
// Launch: 6 GEMMs + 2 softmaxes, all on the default stream (graph-capturable,
// allocation-free; scratch lives in __device__ globals).
// ---------------------------------------------------------------------------
extern "C" void kernel_launch(void* const* d_in, const int* in_sizes, int n_in,
                              void* d_out, int out_size)
{
    const float* query = (const float*)d_in[0];
    const float* key   = (const float*)d_in[1];
    const float* value = (const float*)d_in[2];
    const float* imfe  = (const float*)d_in[3];
    const float* W0 = (const float*)d_in[4];  const float* b0 = (const float*)d_in[5];
    const float* W1 = (const float*)d_in[6];  const float* b1 = (const float*)d_in[7];
    const float* W2 = (const float*)d_in[8];  const float* b2 = (const float*)d_in[9];
    const float* W3 = (const float*)d_in[10]; const float* b3 = (const float*)d_in[11];
    float* out = (float*)d_out;

    float *buf1, *buf2, *kb, *vt, *imft;
    cudaGetSymbolAddress((void**)&buf1, g_buf1);
    cudaGetSymbolAddress((void**)&buf2, g_buf2);
    cudaGetSymbolAddress((void**)&kb,   g_k);
    cudaGetSymbolAddress((void**)&vt,   g_vt);
    cudaGetSymbolAddress((void**)&imft, g_imft);

    const dim3 blk(256);
    const float scl = 1.0f / sqrtf((float)DKc);

    // --- projections ---
    // q = split_heads(query @ W0^T + b0) -> buf1 [b,h,sq,dk]
    gemm_nt<1, SQc><<<dim3(DMc / BN, (Bc * SQc) / BM, 1), blk>>>(
        query, W0, b0, buf1, Bc * SQc, DMc, DMc, 0, 0, 0, 1.f);
    // k -> g_k [b,h,sk,dk]
    gemm_nt<1, SKc><<<dim3(DMc / BN, (Bc * SKc) / BM, 1), blk>>>(
        key, W1, b1, kb, Bc * SKc, DMc, DMc, 0, 0, 0, 1.f);
    // v -> g_vt [b,h,dk,sk] (transposed for second-stage NT contraction)
    gemm_nt<2, SKc><<<dim3(DMc / BN, (Bc * SKc) / BM, 1), blk>>>(
        value, W2, b2, vt, Bc * SKc, DMc, DMc, 0, 0, 0, 1.f);
    // imf -> g_imft [b,h,dk,sk] (transposed)
    gemm_nt<2, SKc><<<dim3(DMc / BN, (Bc * SKc) / BM, 1), blk>>>(
        imfe, W3, b3, imft, Bc * SKc, DMc, DMc, 0, 0, 0, 1.f);

    // --- scores = q @ k^T / sqrt(dk), then softmax over sk -> buf2 ---
    gemm_nt<3, 0><<<dim3(SKc / BN, SQc / BM, Bc * Hc), blk>>>(
        buf1, kb, nullptr, buf2, SQc, SKc, DKc,
        (long long)SQc * DKc, (long long)SKc * DKc, (long long)SQc * SKc, scl);
    softmax512<<<(Bc * Hc * SQc) / 8, 256>>>(buf2, Bc * Hc * SQc);

    // --- t = p_attn @ imf, softmax over d -> im_attn in buf1 (q is dead) ---
    gemm_nt<3, 0><<<dim3(DKc / BN, SQc / BM, Bc * Hc), blk>>>(
        buf2, imft, nullptr, buf1, SQc, DKc, SKc,
        (long long)SQc * SKc, (long long)DKc * SKc, (long long)SQc * DKc, 1.f);
    softmax512<<<(Bc * Hc * SQc) / 8, 256>>>(buf1, Bc * Hc * SQc);

    // --- x = im_attn @ v -> merged heads in buf2 (p_attn is dead) ---
    gemm_nt<4, 0><<<dim3(DKc / BN, SQc / BM, Bc * Hc), blk>>>(
        buf1, vt, nullptr, buf2, SQc, DKc, DKc,
        (long long)SQc * DKc, (long long)DKc * SKc, 0, 1.f);

    // --- out = x @ W3^T + b3 ---
    gemm_nt<0, 0><<<dim3(DMc / BN, (Bc * SQc) / BM, 1), blk>>>(
        buf2, W3, b3, out, Bc * SQc, DMc, DMc, 0, 0, 0, 1.f);
}

// round 12
// speedup vs baseline: 1.0006x; 1.0006x over previous
#include <cuda_runtime.h>
#include <math.h>

// ---------------------------------------------------------------------------
// Problem constants (fixed shapes)
// ---------------------------------------------------------------------------
#define Bc   4
#define Hc   8
#define SQc  2048
#define SKc  512
#define DMc  4096
#define DKc  512

// ---------------------------------------------------------------------------
// Scratch (device globals — allocation-free kernel_launch).
// buf1: q [b,h,sq,dk]  -> later im_attn [b,h,sq,dk]      (33.5M floats)
// buf2: p_attn [b,h,sq,sk] -> later x [b,sq,h*dk]        (33.5M floats)
// ---------------------------------------------------------------------------
__device__ float g_buf1[(size_t)Bc * Hc * SQc * DKc];
__device__ float g_buf2[(size_t)Bc * Hc * SQc * SKc];
__device__ float g_k   [(size_t)Bc * Hc * SKc * DKc];   // k  [b,h,sk,dk]
__device__ float g_vt  [(size_t)Bc * Hc * DKc * SKc];   // v^T [b,h,dk,sk]
__device__ float g_imft[(size_t)Bc * Hc * DKc * SKc];   // imf^T [b,h,dk,sk]

// ---------------------------------------------------------------------------
// SGEMM (NT: C[m,n] = sum_k A[m,k] * B[n,k]), fp32, 128x128x16 tile,
// 256 threads, 8x8 per thread (split 4+4 for conflict-free LDS.128).
// MODE 0: plain row-major + bias                  (output projection)
// MODE 1: split-head [b,h,s,dk] + bias            (q, k projections)
// MODE 2: split-head transposed [b,h,dk,s] + bias (v, imf projections)
// MODE 3: batched plain (z = b*H+h), * scale      (scores / p@imf)
// MODE 4: batched merge-head [b,sq,h*dk]          (im_attn @ v)
// ---------------------------------------------------------------------------
#define BM 128
#define BN 128
#define BK 16
#define PAD 4

template <int MODE, int S>
__global__ void __launch_bounds__(256, 2)
gemm_nt(const float* __restrict__ A, const float* __restrict__ Bm,
        const float* __restrict__ bias, float* __restrict__ C,
        int M, int N, int K,
        long long sA, long long sB, long long sC, float scale)
{
    __shared__ float As[BK][BM + PAD];
    __shared__ float Bs[BK][BN + PAD];

    const int tid = threadIdx.x;
    const int tx  = tid & 15;   // 0..15  (N dir)
    const int ty  = tid >> 4;   // 0..15  (M dir)
    const int m0  = blockIdx.y * BM;
    const int n0  = blockIdx.x * BN;

    const float* Ab = A  + (long long)blockIdx.z * sA;
    const float* Bb = Bm + (long long)blockIdx.z * sB;

    const int lrow = tid >> 2;        // 0..63
    const int lcol = (tid & 3) << 2;  // 0,4,8,12

    float acc[8][8];
#pragma unroll
    for (int i = 0; i < 8; i++)
#pragma unroll
        for (int j = 0; j < 8; j++) acc[i][j] = 0.f;

    for (int k0 = 0; k0 < K; k0 += BK) {
#pragma unroll
        for (int t = 0; t < 2; t++) {
            const int r = lrow + t * 64;
            float4 av = *(const float4*)(Ab + (long long)(m0 + r) * K + k0 + lcol);
            As[lcol + 0][r] = av.x; As[lcol + 1][r] = av.y;
            As[lcol + 2][r] = av.z; As[lcol + 3][r] = av.w;
            float4 bv = *(const float4*)(Bb + (long long)(n0 + r) * K + k0 + lcol);
            Bs[lcol + 0][r] = bv.x; Bs[lcol + 1][r] = bv.y;
            Bs[lcol + 2][r] = bv.z; Bs[lcol + 3][r] = bv.w;
        }
        __syncthreads();

#pragma unroll
        for (int kk = 0; kk < BK; kk++) {
            float a[8], b[8];
            float4 a0 = *(const float4*)&As[kk][ty * 4];
            float4 a1 = *(const float4*)&As[kk][64 + ty * 4];
            a[0] = a0.x; a[1] = a0.y; a[2] = a0.z; a[3] = a0.w;
            a[4] = a1.x; a[5] = a1.y; a[6] = a1.z; a[7] = a1.w;
            float4 b0v = *(const float4*)&Bs[kk][tx * 4];
            float4 b1v = *(const float4*)&Bs[kk][64 + tx * 4];
            b[0] = b0v.x; b[1] = b0v.y; b[2] = b0v.z; b[3] = b0v.w;
            b[4] = b1v.x; b[5] = b1v.y; b[6] = b1v.z; b[7] = b1v.w;
#pragma unroll
            for (int i = 0; i < 8; i++)
#pragma unroll
                for (int j = 0; j < 8; j++)
                    acc[i][j] = fmaf(a[i], b[j], acc[i][j]);
        }
        __syncthreads();
    }

    // --- epilogue: per-thread 8x8, split 4+4 row/col mapping ---
    int rows[8], cols[8];
#pragma unroll
    for (int i = 0; i < 4; i++) {
        rows[i]     = m0 + ty * 4 + i;
        rows[i + 4] = m0 + 64 + ty * 4 + i;
        cols[i]     = n0 + tx * 4 + i;
        cols[i + 4] = n0 + 64 + tx * 4 + i;
    }

    if (MODE == 0) {
#pragma unroll
        for (int i = 0; i < 8; i++) {
            const long long ro = (long long)rows[i] * N;
#pragma unroll
            for (int j = 0; j < 8; j++)
                C[ro + cols[j]] = acc[i][j] + bias[cols[j]];
        }
    } else if (MODE == 1) {
#pragma unroll
        for (int i = 0; i < 8; i++) {
            const int r = rows[i];
            const int bb = r / S, s = r % S;
#pragma unroll
            for (int j = 0; j < 8; j++) {
                const int c = cols[j];
                const int h = c >> 9, dk = c & 511;
                C[(((long long)(bb * Hc + h) * S + s) << 9) + dk] = acc[i][j] + bias[c];
            }
        }
    } else if (MODE == 2) {
#pragma unroll
        for (int i = 0; i < 8; i++) {
            const int r = rows[i];
            const int bb = r / S, s = r % S;
#pragma unroll
            for (int j = 0; j < 8; j++) {
                const int c = cols[j];
                const int h = c >> 9, dk = c & 511;
                C[((long long)(bb * Hc + h) * DKc + dk) * S + s] = acc[i][j] + bias[c];
            }
        }
    } else if (MODE == 3) {
        float* Cb = C + (long long)blockIdx.z * sC;
#pragma unroll
        for (int i = 0; i < 8; i++) {
            const long long ro = (long long)rows[i] * N;
#pragma unroll
            for (int j = 0; j < 8; j++)
                Cb[ro + cols[j]] = acc[i][j] * scale;
        }
    } else {  // MODE 4: merge heads -> [b, sq, h*dk]
        const int z = blockIdx.z;
        const int bb = z >> 3, h = z & 7;
#pragma unroll
        for (int i = 0; i < 8; i++) {
            const long long ro = ((long long)(bb * SQc + rows[i])) * DMc + h * DKc;
#pragma unroll
            for (int j = 0; j < 8; j++)
                C[ro + cols[j]] = acc[i][j];
        }
    }
}

// ---------------------------------------------------------------------------
// Row softmax, row length 512. One warp per row, 16 elems/lane in registers.
// ---------------------------------------------------------------------------
__global__ void softmax512(float* __restrict__ data, int nrows)
{
    const int warp = (blockIdx.x * blockDim.x + threadIdx.x) >> 5;
    const int lane = threadIdx.x & 31;
    if (warp >= nrows) return;
    float* row = data + (long long)warp * 512;

    float v[16];
    float mx = -3.4e38f;
#pragma unroll
    for (int i = 0; i < 16; i++) {
        v[i] = row[lane + i * 32];
        mx = fmaxf(mx, v[i]);
    }
#pragma unroll
    for (int o = 16; o > 0; o >>= 1)
        mx = fmaxf(mx, __shfl_xor_sync(0xffffffffu, mx, o));

    float sum = 0.f;
#pragma unroll
    for (int i = 0; i < 16; i++) {
        v[i] = __expf(v[i] - mx);
        sum += v[i];
    }
#pragma unroll
    for (int o = 16; o > 0; o >>= 1)
        sum += __shfl_xor_sync(0xffffffffu, sum, o);

    const float inv = 1.0f / sum;
#pragma unroll
    for (int i = 0; i < 16; i++)
        row[lane + i * 32] = v[i] * inv;
}

// ---------------------------------------------------------------------------
// Launch: 6 GEMMs + 2 softmaxes, all on the default stream (graph-capturable,
// allocation-free; scratch lives in __device__ globals).
// ---------------------------------------------------------------------------
extern "C" void kernel_launch(void* const* d_in, const int* in_sizes, int n_in,
                              void* d_out, int out_size)
{
    const float* query = (const float*)d_in[0];
    const float* key   = (const float*)d_in[1];
    const float* value = (const float*)d_in[2];
    const float* imfe  = (const float*)d_in[3];
    const float* W0 = (const float*)d_in[4];  const float* b0 = (const float*)d_in[5];
    const float* W1 = (const float*)d_in[6];  const float* b1 = (const float*)d_in[7];
    const float* W2 = (const float*)d_in[8];  const float* b2 = (const float*)d_in[9];
    const float* W3 = (const float*)d_in[10]; const float* b3 = (const float*)d_in[11];
    float* out = (float*)d_out;

    float *buf1, *buf2, *kb, *vt, *imft;
    cudaGetSymbolAddress((void**)&buf1, g_buf1);
    cudaGetSymbolAddress((void**)&buf2, g_buf2);
    cudaGetSymbolAddress((void**)&kb,   g_k);
    cudaGetSymbolAddress((void**)&vt,   g_vt);
    cudaGetSymbolAddress((void**)&imft, g_imft);

    const dim3 blk(256);
    const float scl = 1.0f / sqrtf((float)DKc);

    // --- projections ---
    // q = split_heads(query @ W0^T + b0) -> buf1 [b,h,sq,dk]
    gemm_nt<1, SQc><<<dim3(DMc / BN, (Bc * SQc) / BM, 1), blk>>>(
        query, W0, b0, buf1, Bc * SQc, DMc, DMc, 0, 0, 0, 1.f);
    // k -> g_k [b,h,sk,dk]
    gemm_nt<1, SKc><<<dim3(DMc / BN, (Bc * SKc) / BM, 1), blk>>>(
        key, W1, b1, kb, Bc * SKc, DMc, DMc, 0, 0, 0, 1.f);
    // v -> g_vt [b,h,dk,sk] (transposed for second-stage NT contraction)
    gemm_nt<2, SKc><<<dim3(DMc / BN, (Bc * SKc) / BM, 1), blk>>>(
        value, W2, b2, vt, Bc * SKc, DMc, DMc, 0, 0, 0, 1.f);
    // imf -> g_imft [b,h,dk,sk] (transposed)
    gemm_nt<2, SKc><<<dim3(DMc / BN, (Bc * SKc) / BM, 1), blk>>>(
        imfe, W3, b3, imft, Bc * SKc, DMc, DMc, 0, 0, 0, 1.f);

    // --- scores = q @ k^T / sqrt(dk), then softmax over sk -> buf2 ---
    gemm_nt<3, 0><<<dim3(SKc / BN, SQc / BM, Bc * Hc), blk>>>(
        buf1, kb, nullptr, buf2, SQc, SKc, DKc,
        (long long)SQc * DKc, (long long)SKc * DKc, (long long)SQc * SKc, scl);
    softmax512<<<(Bc * Hc * SQc) / 8, 256>>>(buf2, Bc * Hc * SQc);

    // --- t = p_attn @ imf, softmax over d -> im_attn in buf1 (q is dead) ---
    gemm_nt<3, 0><<<dim3(DKc / BN, SQc / BM, Bc * Hc), blk>>>(
        buf2, imft, nullptr, buf1, SQc, DKc, SKc,
        (long long)SQc * SKc, (long long)DKc * SKc, (long long)SQc * DKc, 1.f);
    softmax512<<<(Bc * Hc * SQc) / 8, 256>>>(buf1, Bc * Hc * SQc);

    // --- x = im_attn @ v -> merged heads in buf2 (p_attn is dead) ---
    gemm_nt<4, 0><<<dim3(DKc / BN, SQc / BM, Bc * Hc), blk>>>(
        buf1, vt, nullptr, buf2, SQc, DKc, DKc,
        (long long)SQc * DKc, (long long)DKc * SKc, 0, 1.f);

    // --- out = x @ W3^T + b3 ---
    gemm_nt<0, 0><<<dim3(DMc / BN, (Bc * SQc) / BM, 1), blk>>>(
        buf2, W3, b3, out, Bc * SQc, DMc, DMc, 0, 0, 0, 1.f);
}

// round 13
// speedup vs baseline: 1.0008x; 1.0002x over previous
#include <cuda_runtime.h>
#include <math.h>

// ---------------------------------------------------------------------------
// Problem constants (fixed shapes)
// ---------------------------------------------------------------------------
#define Bc   4
#define Hc   8
#define SQc  2048
#define SKc  512
#define DMc  4096
#define DKc  512

// ---------------------------------------------------------------------------
// Scratch (device globals — allocation-free kernel_launch).
// buf1: q [b,h,sq,dk]  -> later im_attn [b,h,sq,dk]      (33.5M floats)
// buf2: p_attn [b,h,sq,sk] -> later x [b,sq,h*dk]        (33.5M floats)
// ---------------------------------------------------------------------------
__device__ float g_buf1[(size_t)Bc * Hc * SQc * DKc];
__device__ float g_buf2[(size_t)Bc * Hc * SQc * SKc];
__device__ float g_k   [(size_t)Bc * Hc * SKc * DKc];   // k  [b,h,sk,dk]
__device__ float g_vt  [(size_t)Bc * Hc * DKc * SKc];   // v^T [b,h,dk,sk]
__device__ float g_imft[(size_t)Bc * Hc * DKc * SKc];   // imf^T [b,h,dk,sk]

// ---------------------------------------------------------------------------
// SGEMM (NT: C[m,n] = sum_k A[m,k] * B[n,k]), fp32, 128x128x16 tile,
// 256 threads, 8x8 per thread (split 4+4 for conflict-free LDS.128).
// MODE 0: plain row-major + bias                  (output projection)
// MODE 1: split-head [b,h,s,dk] + bias            (q, k projections)
// MODE 2: split-head transposed [b,h,dk,s] + bias (v, imf projections)
// MODE 3: batched plain (z = b*H+h), * scale      (scores / p@imf)
// MODE 4: batched merge-head [b,sq,h*dk]          (im_attn @ v)
// ---------------------------------------------------------------------------
#define BM 128
#define BN 128
#define BK 16
#define PAD 4

template <int MODE, int S>
__global__ void __launch_bounds__(256, 2)
gemm_nt(const float* __restrict__ A, const float* __restrict__ Bm,
        const float* __restrict__ bias, float* __restrict__ C,
        int M, int N, int K,
        long long sA, long long sB, long long sC, float scale)
{
    __shared__ float As[BK][BM + PAD];
    __shared__ float Bs[BK][BN + PAD];

    const int tid = threadIdx.x;
    const int tx  = tid & 15;   // 0..15  (N dir)
    const int ty  = tid >> 4;   // 0..15  (M dir)
    const int m0  = blockIdx.y * BM;
    const int n0  = blockIdx.x * BN;

    const float* Ab = A  + (long long)blockIdx.z * sA;
    const float* Bb = Bm + (long long)blockIdx.z * sB;

    const int lrow = tid >> 2;        // 0..63
    const int lcol = (tid & 3) << 2;  // 0,4,8,12

    float acc[8][8];
#pragma unroll
    for (int i = 0; i < 8; i++)
#pragma unroll
        for (int j = 0; j < 8; j++) acc[i][j] = 0.f;

    for (int k0 = 0; k0 < K; k0 += BK) {
#pragma unroll
        for (int t = 0; t < 2; t++) {
            const int r = lrow + t * 64;
            float4 av = *(const float4*)(Ab + (long long)(m0 + r) * K + k0 + lcol);
            As[lcol + 0][r] = av.x; As[lcol + 1][r] = av.y;
            As[lcol + 2][r] = av.z; As[lcol + 3][r] = av.w;
            float4 bv = *(const float4*)(Bb + (long long)(n0 + r) * K + k0 + lcol);
            Bs[lcol + 0][r] = bv.x; Bs[lcol + 1][r] = bv.y;
            Bs[lcol + 2][r] = bv.z; Bs[lcol + 3][r] = bv.w;
        }
        __syncthreads();

#pragma unroll
        for (int kk = 0; kk < BK; kk++) {
            float a[8], b[8];
            float4 a0 = *(const float4*)&As[kk][ty * 4];
            float4 a1 = *(const float4*)&As[kk][64 + ty * 4];
            a[0] = a0.x; a[1] = a0.y; a[2] = a0.z; a[3] = a0.w;
            a[4] = a1.x; a[5] = a1.y; a[6] = a1.z; a[7] = a1.w;
            float4 b0v = *(const float4*)&Bs[kk][tx * 4];
            float4 b1v = *(const float4*)&Bs[kk][64 + tx * 4];
            b[0] = b0v.x; b[1] = b0v.y; b[2] = b0v.z; b[3] = b0v.w;
            b[4] = b1v.x; b[5] = b1v.y; b[6] = b1v.z; b[7] = b1v.w;
#pragma unroll
            for (int i = 0; i < 8; i++)
#pragma unroll
                for (int j = 0; j < 8; j++)
                    acc[i][j] = fmaf(a[i], b[j], acc[i][j]);
        }
        __syncthreads();
    }

    // --- epilogue: per-thread 8x8, split 4+4 row/col mapping ---
    int rows[8], cols[8];
#pragma unroll
    for (int i = 0; i < 4; i++) {
        rows[i]     = m0 + ty * 4 + i;
        rows[i + 4] = m0 + 64 + ty * 4 + i;
        cols[i]     = n0 + tx * 4 + i;
        cols[i + 4] = n0 + 64 + tx * 4 + i;
    }

    if (MODE == 0) {
#pragma unroll
        for (int i = 0; i < 8; i++) {
            const long long ro = (long long)rows[i] * N;
#pragma unroll
            for (int j = 0; j < 8; j++)
                C[ro + cols[j]] = acc[i][j] + bias[cols[j]];
        }
    } else if (MODE == 1) {
#pragma unroll
        for (int i = 0; i < 8; i++) {
            const int r = rows[i];
            const int bb = r / S, s = r % S;
#pragma unroll
            for (int j = 0; j < 8; j++) {
                const int c = cols[j];
                const int h = c >> 9, dk = c & 511;
                C[(((long long)(bb * Hc + h) * S + s) << 9) + dk] = acc[i][j] + bias[c];
            }
        }
    } else if (MODE == 2) {
#pragma unroll
        for (int i = 0; i < 8; i++) {
            const int r = rows[i];
            const int bb = r / S, s = r % S;
#pragma unroll
            for (int j = 0; j < 8; j++) {
                const int c = cols[j];
                const int h = c >> 9, dk = c & 511;
                C[((long long)(bb * Hc + h) * DKc + dk) * S + s] = acc[i][j] + bias[c];
            }
        }
    } else if (MODE == 3) {
        float* Cb = C + (long long)blockIdx.z * sC;
#pragma unroll
        for (int i = 0; i < 8; i++) {
            const long long ro = (long long)rows[i] * N;
#pragma unroll
            for (int j = 0; j < 8; j++)
                Cb[ro + cols[j]] = acc[i][j] * scale;
        }
    } else {  // MODE 4: merge heads -> [b, sq, h*dk]
        const int z = blockIdx.z;
        const int bb = z >> 3, h = z & 7;
#pragma unroll
        for (int i = 0; i < 8; i++) {
            const long long ro = ((long long)(bb * SQc + rows[i])) * DMc + h * DKc;
#pragma unroll
            for (int j = 0; j < 8; j++)
                C[ro + cols[j]] = acc[i][j];
        }
    }
}

// ---------------------------------------------------------------------------
// Row softmax, row length 512. One warp per row, 16 elems/lane in registers.
// ---------------------------------------------------------------------------
__global__ void softmax512(float* __restrict__ data, int nrows)
{
    const int warp = (blockIdx.x * blockDim.x + threadIdx.x) >> 5;
    const int lane = threadIdx.x & 31;
    if (warp >= nrows) return;
    float* row = data + (long long)warp * 512;

    float v[16];
    float mx = -3.4e38f;
#pragma unroll
    for (int i = 0; i < 16; i++) {
        v[i] = row[lane + i * 32];
        mx = fmaxf(mx, v[i]);
    }
#pragma unroll
    for (int o = 16; o > 0; o >>= 1)
        mx = fmaxf(mx, __shfl_xor_sync(0xffffffffu, mx, o));

    float sum = 0.f;
#pragma unroll
    for (int i = 0; i < 16; i++) {
        v[i] = __expf(v[i] - mx);
        sum += v[i];
    }
#pragma unroll
    for (int o = 16; o > 0; o >>= 1)
        sum += __shfl_xor_sync(0xffffffffu, sum, o);

    const float inv = 1.0f / sum;
#pragma unroll
    for (int i = 0; i < 16; i++)
        row[lane + i * 32] = v[i] * inv;
}

// ---------------------------------------------------------------------------
// Launch: 6 GEMMs + 2 softmaxes, all on the default stream (graph-capturable,
// allocation-free; scratch lives in __device__ globals).
// ---------------------------------------------------------------------------
extern "C" void kernel_launch(void* const* d_in, const int* in_sizes, int n_in,
                              void* d_out, int out_size)
{
    const float* query = (const float*)d_in[0];
    const float* key   = (const float*)d_in[1];
    const float* value = (const float*)d_in[2];
    const float* imfe  = (const float*)d_in[3];
    const float* W0 = (const float*)d_in[4];  const float* b0 = (const float*)d_in[5];
    const float* W1 = (const float*)d_in[6];  const float* b1 = (const float*)d_in[7];
    const float* W2 = (const float*)d_in[8];  const float* b2 = (const float*)d_in[9];
    const float* W3 = (const float*)d_in[10]; const float* b3 = (const float*)d_in[11];
    float* out = (float*)d_out;

    float *buf1, *buf2, *kb, *vt, *imft;
    cudaGetSymbolAddress((void**)&buf1, g_buf1);
    cudaGetSymbolAddress((void**)&buf2, g_buf2);
    cudaGetSymbolAddress((void**)&kb,   g_k);
    cudaGetSymbolAddress((void**)&vt,   g_vt);
    cudaGetSymbolAddress((void**)&imft, g_imft);

    const dim3 blk(256);
    const float scl = 1.0f / sqrtf((float)DKc);

    // --- projections ---
    // q = split_heads(query @ W0^T + b0) -> buf1 [b,h,sq,dk]
    gemm_nt<1, SQc><<<dim3(DMc / BN, (Bc * SQc) / BM, 1), blk>>>(
        query, W0, b0, buf1, Bc * SQc, DMc, DMc, 0, 0, 0, 1.f);
    // k -> g_k [b,h,sk,dk]
    gemm_nt<1, SKc><<<dim3(DMc / BN, (Bc * SKc) / BM, 1), blk>>>(
        key, W1, b1, kb, Bc * SKc, DMc, DMc, 0, 0, 0, 1.f);
    // v -> g_vt [b,h,dk,sk] (transposed for second-stage NT contraction)
    gemm_nt<2, SKc><<<dim3(DMc / BN, (Bc * SKc) / BM, 1), blk>>>(
        value, W2, b2, vt, Bc * SKc, DMc, DMc, 0, 0, 0, 1.f);
    // imf -> g_imft [b,h,dk,sk] (transposed)
    gemm_nt<2, SKc><<<dim3(DMc / BN, (Bc * SKc) / BM, 1), blk>>>(
        imfe, W3, b3, imft, Bc * SKc, DMc, DMc, 0, 0, 0, 1.f);

    // --- scores = q @ k^T / sqrt(dk), then softmax over sk -> buf2 ---
    gemm_nt<3, 0><<<dim3(SKc / BN, SQc / BM, Bc * Hc), blk>>>(
        buf1, kb, nullptr, buf2, SQc, SKc, DKc,
        (long long)SQc * DKc, (long long)SKc * DKc, (long long)SQc * SKc, scl);
    softmax512<<<(Bc * Hc * SQc) / 8, 256>>>(buf2, Bc * Hc * SQc);

    // --- t = p_attn @ imf, softmax over d -> im_attn in buf1 (q is dead) ---
    gemm_nt<3, 0><<<dim3(DKc / BN, SQc / BM, Bc * Hc), blk>>>(
        buf2, imft, nullptr, buf1, SQc, DKc, SKc,
        (long long)SQc * SKc, (long long)DKc * SKc, (long long)SQc * DKc, 1.f);
    softmax512<<<(Bc * Hc * SQc) / 8, 256>>>(buf1, Bc * Hc * SQc);

    // --- x = im_attn @ v -> merged heads in buf2 (p_attn is dead) ---
    gemm_nt<4, 0><<<dim3(DKc / BN, SQc / BM, Bc * Hc), blk>>>(
        buf1, vt, nullptr, buf2, SQc, DKc, DKc,
        (long long)SQc * DKc, (long long)DKc * SKc, 0, 1.f);

    // --- out = x @ W3^T + b3 ---
    gemm_nt<0, 0><<<dim3(DMc / BN, (Bc * SQc) / BM, 1), blk>>>(
        buf2, W3, b3, out, Bc * SQc, DMc, DMc, 0, 0, 0, 1.f);
}

// round 15
// speedup vs baseline: 3.2075x; 3.2050x over previous
#include <cuda_runtime.h>
#include <math.h>
#include <stdint.h>

// ---------------------------------------------------------------------------
// Problem constants
// ---------------------------------------------------------------------------
#define Bc   4
#define Hc   8
#define SQc  2048
#define SKc  512
#define DMc  4096
#define DKc  512

// ---------------------------------------------------------------------------
// Scratch (device globals — allocation-free kernel_launch)
// ---------------------------------------------------------------------------
__device__ float g_buf1[(size_t)Bc * Hc * SQc * DKc];   // q -> im_attn
__device__ float g_buf2[(size_t)Bc * Hc * SQc * SKc];   // p_attn -> x
__device__ float g_k   [(size_t)Bc * Hc * SKc * DKc];   // k   [b,h,sk,dk]
__device__ float g_vt  [(size_t)Bc * Hc * DKc * SKc];   // v^T [b,h,dk,sk]
__device__ float g_imft[(size_t)Bc * Hc * DKc * SKc];   // imf^T
// tf32-rounded copies of raw inputs + weights (rounded once, outside GEMMs)
__device__ float g_qi[(size_t)Bc * SQc * DMc];
__device__ float g_ki[(size_t)Bc * SKc * DMc];
__device__ float g_vi[(size_t)Bc * SKc * DMc];
__device__ float g_ii[(size_t)Bc * SKc * DMc];
__device__ float g_w0[(size_t)DMc * DMc];
__device__ float g_w1[(size_t)DMc * DMc];
__device__ float g_w2[(size_t)DMc * DMc];
__device__ float g_w3[(size_t)DMc * DMc];

// ---------------------------------------------------------------------------
// Helpers
// ---------------------------------------------------------------------------
__device__ __forceinline__ uint32_t smem_u32(const void* p) {
    uint32_t a;
    asm("{ .reg .u64 t; cvta.to.shared.u64 t, %1; cvt.u32.u64 %0, t; }" : "=r"(a) : "l"(p));
    return a;
}
__device__ __forceinline__ float tf32r(float f) {
    uint32_t r;
    asm("cvt.rna.tf32.f32 %0, %1;" : "=r"(r) : "f"(f));
    return __uint_as_float(r);
}
__device__ __forceinline__ void cp16(uint32_t dst, const float* src) {
    asm volatile("cp.async.cg.shared.global [%0], [%1], 16;" :: "r"(dst), "l"(src) : "memory");
}
#define CP_COMMIT() asm volatile("cp.async.commit_group;" ::: "memory")
#define CP_WAIT1()  asm volatile("cp.async.wait_group 1;" ::: "memory")

// ---------------------------------------------------------------------------
// tf32 mma.sync GEMM (NT: C[m,n] = sum_k A[m,k]*B[n,k])
// CTA tile 128x128x32, 8 warps (4x2), warp tile 32x64, m16n8k8.
// smem rows padded to 36 floats (conflict-free fragment loads).
// 3-stage cp.async pipeline.
// MODE 0: plain + bias (out proj, no rounding)
// MODE 1: split-head [b,h,s,dk] + bias, tf32-rounded (q,k)
// MODE 2: split-head transposed [b,h,dk,s] + bias, tf32-rounded (v,imf)
// MODE 3: batched plain * scale (scores / p@imf; feeds softmax, no rounding)
// MODE 4: batched merge-head [b,sq,h*dk], tf32-rounded (x)
// ---------------------------------------------------------------------------
#define BM 128
#define BN 128
#define BKT 32
#define LROW 36                      // padded row stride in floats
#define TILE_F (128 * LROW)          // 4608 floats per A or B tile
#define STAGE_F (2 * TILE_F)         // 9216 floats per stage
#define NSTAGE 3
#define GEMM_SMEM (NSTAGE * STAGE_F * 4)   // 110592 bytes

template <int MODE, int S>
__global__ void __launch_bounds__(256, 2)
tgemm(const float* __restrict__ A, const float* __restrict__ Bm,
      const float* __restrict__ bias, float* __restrict__ C,
      int M, int N, int K, long long sA, long long sB, long long sC, float scale)
{
    extern __shared__ float sm[];
    const uint32_t sbase = smem_u32(sm);
    const int tid = threadIdx.x;
    const int m0 = blockIdx.y * BM;
    const int n0 = blockIdx.x * BN;
    const int z  = blockIdx.z;

    const float* Ab = A  + (long long)z * sA;
    const float* Bb = Bm + (long long)z * sB;

    // loader geometry: 4 rows x 16B per thread per tile
    const int lrow = tid >> 3;       // 0..31
    const int lc16 = tid & 7;        // 16B chunk in 128B row

    // compute geometry
    const int lane = tid & 31, wid = tid >> 5;
    const int g = lane >> 2, tg = lane & 3;
    const int wm = wid & 3, wn = wid >> 2;   // 4x2 warp grid

    float acc[2][8][4];
#pragma unroll
    for (int mt = 0; mt < 2; mt++)
#pragma unroll
        for (int nt = 0; nt < 8; nt++)
#pragma unroll
            for (int r = 0; r < 4; r++) acc[mt][nt][r] = 0.f;

    const int T = K >> 5;

    // ---- issue loads for one stage ----
    auto issue = [&](int slot, int k0) {
        const uint32_t ab = sbase + (uint32_t)slot * STAGE_F * 4;
        const uint32_t bb2 = ab + TILE_F * 4;
#pragma unroll
        for (int i = 0; i < 4; i++) {
            const int row = lrow + 32 * i;
            cp16(ab  + row * (LROW * 4) + lc16 * 16,
                 Ab + (long long)(m0 + row) * K + k0 + lc16 * 4);
            cp16(bb2 + row * (LROW * 4) + lc16 * 16,
                 Bb + (long long)(n0 + row) * K + k0 + lc16 * 4);
        }
        CP_COMMIT();
    };

    issue(0, 0);
    issue(1, 32);

    for (int t = 0; t < T; t++) {
        CP_WAIT1();               // tile t resident
        __syncthreads();
        if (t + 2 < T) issue((t + 2) % 3, (t + 2) * 32);
        else CP_COMMIT();         // empty group keeps the wait-count invariant

        const uint32_t* Asu = (const uint32_t*)(sm + (t % 3) * STAGE_F);
        const uint32_t* Bsu = Asu + TILE_F;

#pragma unroll
        for (int kk = 0; kk < 4; kk++) {
            const int k = kk * 8;
            uint32_t a[2][4];
#pragma unroll
            for (int mt = 0; mt < 2; mt++) {
                const int r = wm * 32 + mt * 16 + g;
                a[mt][0] = Asu[r * LROW + k + tg];
                a[mt][1] = Asu[(r + 8) * LROW + k + tg];
                a[mt][2] = Asu[r * LROW + k + tg + 4];
                a[mt][3] = Asu[(r + 8) * LROW + k + tg + 4];
            }
            uint32_t b[8][2];
#pragma unroll
            for (int nt = 0; nt < 8; nt++) {
                const int c = wn * 64 + nt * 8 + g;
                b[nt][0] = Bsu[c * LROW + k + tg];
                b[nt][1] = Bsu[c * LROW + k + tg + 4];
            }
#pragma unroll
            for (int mt = 0; mt < 2; mt++)
#pragma unroll
                for (int nt = 0; nt < 8; nt++)
                    asm volatile(
                        "mma.sync.aligned.m16n8k8.row.col.f32.tf32.tf32.f32 "
                        "{%0,%1,%2,%3}, {%4,%5,%6,%7}, {%8,%9}, {%0,%1,%2,%3};"
                        : "+f"(acc[mt][nt][0]), "+f"(acc[mt][nt][1]),
                          "+f"(acc[mt][nt][2]), "+f"(acc[mt][nt][3])
                        : "r"(a[mt][0]), "r"(a[mt][1]), "r"(a[mt][2]), "r"(a[mt][3]),
                          "r"(b[nt][0]), "r"(b[nt][1]));
        }
    }

    // ---- epilogue ----
#pragma unroll
    for (int mt = 0; mt < 2; mt++) {
#pragma unroll
        for (int j = 0; j < 2; j++) {
            const int rabs = m0 + wm * 32 + mt * 16 + g + 8 * j;
#pragma unroll
            for (int nt = 0; nt < 8; nt++) {
                const int cabs = n0 + wn * 64 + nt * 8 + tg * 2;
                const float v0 = acc[mt][nt][2 * j + 0];
                const float v1 = acc[mt][nt][2 * j + 1];

                if (MODE == 0) {
                    float2 o = make_float2(v0 + bias[cabs], v1 + bias[cabs + 1]);
                    *(float2*)(C + (long long)rabs * N + cabs) = o;
                } else if (MODE == 1) {
                    const int bb = rabs / S, s = rabs % S;
                    const int h = cabs >> 9, dk = cabs & 511;
                    float2 o = make_float2(tf32r(v0 + bias[cabs]),
                                           tf32r(v1 + bias[cabs + 1]));
                    *(float2*)(C + (((long long)(bb * Hc + h) * S + s) << 9) + dk) = o;
                } else if (MODE == 2) {
                    const int bb = rabs / S, s = rabs % S;
                    const int h = cabs >> 9, dk = cabs & 511;
                    float* base = C + ((long long)(bb * Hc + h) * DKc + dk) * S + s;
                    base[0]          = tf32r(v0 + bias[cabs]);
                    base[(long long)S] = tf32r(v1 + bias[cabs + 1]);
                } else if (MODE == 3) {
                    float2 o = make_float2(v0 * scale, v1 * scale);
                    *(float2*)(C + (long long)z * sC + (long long)rabs * N + cabs) = o;
                } else {  // MODE 4
                    const int bb = z >> 3, h = z & 7;
                    float2 o = make_float2(tf32r(v0), tf32r(v1));
                    *(float2*)(C + (long long)(bb * SQc + rabs) * DMc + h * DKc + cabs) = o;
                }
            }
        }
    }
}

// ---------------------------------------------------------------------------
// Elementwise tf32 rounding copy (inputs / weights)
// ---------------------------------------------------------------------------
__global__ void cvt_tf32(const float* __restrict__ in, float* __restrict__ out, int n4)
{
    int i = blockIdx.x * blockDim.x + threadIdx.x;
    if (i < n4) {
        float4 v = ((const float4*)in)[i];
        float4 o;
        o.x = tf32r(v.x); o.y = tf32r(v.y); o.z = tf32r(v.z); o.w = tf32r(v.w);
        ((float4*)out)[i] = o;
    }
}

// ---------------------------------------------------------------------------
// Row softmax, 512 elems/row, one warp per row; output tf32-rounded
// (it always feeds a tf32 GEMM operand).
// ---------------------------------------------------------------------------
__global__ void softmax512(float* __restrict__ data, int nrows)
{
    const int warp = (blockIdx.x * blockDim.x + threadIdx.x) >> 5;
    const int lane = threadIdx.x & 31;
    if (warp >= nrows) return;
    float* row = data + (long long)warp * 512;

    float v[16];
    float mx = -3.4e38f;
#pragma unroll
    for (int i = 0; i < 16; i++) { v[i] = row[lane + i * 32]; mx = fmaxf(mx, v[i]); }
#pragma unroll
    for (int o = 16; o > 0; o >>= 1) mx = fmaxf(mx, __shfl_xor_sync(0xffffffffu, mx, o));
    float sum = 0.f;
#pragma unroll
    for (int i = 0; i < 16; i++) { v[i] = __expf(v[i] - mx); sum += v[i]; }
#pragma unroll
    for (int o = 16; o > 0; o >>= 1) sum += __shfl_xor_sync(0xffffffffu, sum, o);
    const float inv = 1.0f / sum;
#pragma unroll
    for (int i = 0; i < 16; i++) row[lane + i * 32] = tf32r(v[i] * inv);
}

// ---------------------------------------------------------------------------
// Launch
// ---------------------------------------------------------------------------
extern "C" void kernel_launch(void* const* d_in, const int* in_sizes, int n_in,
                              void* d_out, int out_size)
{
    const float* query = (const float*)d_in[0];
    const float* key   = (const float*)d_in[1];
    const float* value = (const float*)d_in[2];
    const float* imfe  = (const float*)d_in[3];
    const float* W0 = (const float*)d_in[4];  const float* b0 = (const float*)d_in[5];
    const float* W1 = (const float*)d_in[6];  const float* b1 = (const float*)d_in[7];
    const float* W2 = (const float*)d_in[8];  const float* b2 = (const float*)d_in[9];
    const float* W3 = (const float*)d_in[10]; const float* b3 = (const float*)d_in[11];
    float* out = (float*)d_out;

    float *buf1, *buf2, *kb, *vt, *imft;
    float *qi, *ki, *vi, *ii, *w0, *w1, *w2, *w3;
    cudaGetSymbolAddress((void**)&buf1, g_buf1);
    cudaGetSymbolAddress((void**)&buf2, g_buf2);
    cudaGetSymbolAddress((void**)&kb,   g_k);
    cudaGetSymbolAddress((void**)&vt,   g_vt);
    cudaGetSymbolAddress((void**)&imft, g_imft);
    cudaGetSymbolAddress((void**)&qi, g_qi);
    cudaGetSymbolAddress((void**)&ki, g_ki);
    cudaGetSymbolAddress((void**)&vi, g_vi);
    cudaGetSymbolAddress((void**)&ii, g_ii);
    cudaGetSymbolAddress((void**)&w0, g_w0);
    cudaGetSymbolAddress((void**)&w1, g_w1);
    cudaGetSymbolAddress((void**)&w2, g_w2);
    cudaGetSymbolAddress((void**)&w3, g_w3);

    cudaFuncSetAttribute(tgemm<0, 0>,   cudaFuncAttributeMaxDynamicSharedMemorySize, GEMM_SMEM);
    cudaFuncSetAttribute(tgemm<1, SQc>, cudaFuncAttributeMaxDynamicSharedMemorySize, GEMM_SMEM);
    cudaFuncSetAttribute(tgemm<1, SKc>, cudaFuncAttributeMaxDynamicSharedMemorySize, GEMM_SMEM);
    cudaFuncSetAttribute(tgemm<2, SKc>, cudaFuncAttributeMaxDynamicSharedMemorySize, GEMM_SMEM);
    cudaFuncSetAttribute(tgemm<3, 0>,   cudaFuncAttributeMaxDynamicSharedMemorySize, GEMM_SMEM);
    cudaFuncSetAttribute(tgemm<4, 0>,   cudaFuncAttributeMaxDynamicSharedMemorySize, GEMM_SMEM);

    const dim3 blk(256);
    const float scl = 1.0f / sqrtf((float)DKc);

    // ---- tf32-round raw inputs + weights (once) ----
    const int NQ = Bc * SQc * DMc, NK = Bc * SKc * DMc, NW = DMc * DMc;
    cvt_tf32<<<(NQ / 4 + 255) / 256, 256>>>(query, qi, NQ / 4);
    cvt_tf32<<<(NK / 4 + 255) / 256, 256>>>(key,   ki, NK / 4);
    cvt_tf32<<<(NK / 4 + 255) / 256, 256>>>(value, vi, NK / 4);
    cvt_tf32<<<(NK / 4 + 255) / 256, 256>>>(imfe,  ii, NK / 4);
    cvt_tf32<<<(NW / 4 + 255) / 256, 256>>>(W0, w0, NW / 4);
    cvt_tf32<<<(NW / 4 + 255) / 256, 256>>>(W1, w1, NW / 4);
    cvt_tf32<<<(NW / 4 + 255) / 256, 256>>>(W2, w2, NW / 4);
    cvt_tf32<<<(NW / 4 + 255) / 256, 256>>>(W3, w3, NW / 4);

    // ---- projections ----
    tgemm<1, SQc><<<dim3(DMc / BN, (Bc * SQc) / BM, 1), blk, GEMM_SMEM>>>(
        qi, w0, b0, buf1, Bc * SQc, DMc, DMc, 0, 0, 0, 1.f);
    tgemm<1, SKc><<<dim3(DMc / BN, (Bc * SKc) / BM, 1), blk, GEMM_SMEM>>>(
        ki, w1, b1, kb, Bc * SKc, DMc, DMc, 0, 0, 0, 1.f);
    tgemm<2, SKc><<<dim3(DMc / BN, (Bc * SKc) / BM, 1), blk, GEMM_SMEM>>>(
        vi, w2, b2, vt, Bc * SKc, DMc, DMc, 0, 0, 0, 1.f);
    tgemm<2, SKc><<<dim3(DMc / BN, (Bc * SKc) / BM, 1), blk, GEMM_SMEM>>>(
        ii, w3, b3, imft, Bc * SKc, DMc, DMc, 0, 0, 0, 1.f);

    // ---- scores = q @ k^T * scl -> softmax -> p_attn (buf2) ----
    tgemm<3, 0><<<dim3(SKc / BN, SQc / BM, Bc * Hc), blk, GEMM_SMEM>>>(
        buf1, kb, nullptr, buf2, SQc, SKc, DKc,
        (long long)SQc * DKc, (long long)SKc * DKc, (long long)SQc * SKc, scl);
    softmax512<<<(Bc * Hc * SQc) / 8, 256>>>(buf2, Bc * Hc * SQc);

    // ---- t = p_attn @ imf -> softmax -> im_attn (buf1) ----
    tgemm<3, 0><<<dim3(DKc / BN, SQc / BM, Bc * Hc), blk, GEMM_SMEM>>>(
        buf2, imft, nullptr, buf1, SQc, DKc, SKc,
        (long long)SQc * SKc, (long long)DKc * SKc, (long long)SQc * DKc, 1.f);
    softmax512<<<(Bc * Hc * SQc) / 8, 256>>>(buf1, Bc * Hc * SQc);

    // ---- x = im_attn @ v (merge heads -> buf2) ----
    tgemm<4, 0><<<dim3(DKc / BN, SQc / BM, Bc * Hc), blk, GEMM_SMEM>>>(
        buf1, vt, nullptr, buf2, SQc, DKc, DKc,
        (long long)SQc * DKc, (long long)DKc * SKc, 0, 1.f);

    // ---- out = x @ W3^T + b3 ----
    tgemm<0, 0><<<dim3(DMc / BN, (Bc * SQc) / BM, 1), blk, GEMM_SMEM>>>(
        buf2, w3, b3, out, Bc * SQc, DMc, DMc, 0, 0, 0, 1.f);
}

// round 16
// speedup vs baseline: 4.8314x; 1.5063x over previous
#include <cuda_runtime.h>
#include <cuda_fp16.h>
#include <math.h>
#include <stdint.h>

// ---------------------------------------------------------------------------
// Problem constants
// ---------------------------------------------------------------------------
#define Bc   4
#define Hc   8
#define SQc  2048
#define SKc  512
#define DMc  4096
#define DKc  512

// ---------------------------------------------------------------------------
// Scratch (device globals). All GEMM operands live in fp16.
// ---------------------------------------------------------------------------
__device__ __half g_qh[(size_t)Bc * SQc * DMc];        // fp16 inputs
__device__ __half g_kh[(size_t)Bc * SKc * DMc];
__device__ __half g_vh[(size_t)Bc * SKc * DMc];
__device__ __half g_ih[(size_t)Bc * SKc * DMc];
__device__ __half g_w0h[(size_t)DMc * DMc];            // fp16 weights
__device__ __half g_w1h[(size_t)DMc * DMc];
__device__ __half g_w2h[(size_t)DMc * DMc];
__device__ __half g_w3h[(size_t)DMc * DMc];
__device__ __half g_q   [(size_t)Bc * Hc * SQc * DKc]; // q [b,h,sq,dk]
__device__ __half g_kp  [(size_t)Bc * Hc * SKc * DKc]; // k [b,h,sk,dk]
__device__ __half g_vt  [(size_t)Bc * Hc * DKc * SKc]; // v^T [b,h,dk,sk]
__device__ __half g_imft[(size_t)Bc * Hc * DKc * SKc]; // imf^T
__device__ __half g_sc  [(size_t)Bc * Hc * SQc * SKc]; // scores -> p_attn
__device__ __half g_t   [(size_t)Bc * Hc * SQc * DKc]; // t -> im_attn
__device__ __half g_x   [(size_t)Bc * SQc * DMc];      // merged x

// ---------------------------------------------------------------------------
// Helpers
// ---------------------------------------------------------------------------
__device__ __forceinline__ uint32_t smem_u32(const void* p) {
    uint32_t a;
    asm("{ .reg .u64 t; cvta.to.shared.u64 t, %1; cvt.u32.u64 %0, t; }" : "=r"(a) : "l"(p));
    return a;
}
__device__ __forceinline__ void cp16(uint32_t dst, const __half* src) {
    asm volatile("cp.async.cg.shared.global [%0], [%1], 16;" :: "r"(dst), "l"(src) : "memory");
}
#define CP_COMMIT() asm volatile("cp.async.commit_group;" ::: "memory")
#define CP_WAIT1()  asm volatile("cp.async.wait_group 1;" ::: "memory")
#define LDSM4(r0, r1, r2, r3, addr)                                            \
    asm volatile("ldmatrix.sync.aligned.m8n8.x4.shared.b16 {%0,%1,%2,%3}, [%4];" \
        : "=r"(r0), "=r"(r1), "=r"(r2), "=r"(r3) : "r"(addr))

// ---------------------------------------------------------------------------
// fp16 mma.sync GEMM (NT: C[m,n] = sum_k A[m,k]*B[n,k]), fp32 accum.
// CTA tile 128x128x32, 8 warps (4x2), warp tile 32x64, m16n8k16, ldmatrix.x4.
// smem rows padded to 40 halves (80B = 5x16B -> conflict-free LDSM phases).
// 3-stage cp.async pipeline.
// MODE 0: plain fp32 + bias (out proj)
// MODE 1: split-head [b,h,s,dk] + bias -> fp16 (q,k)
// MODE 2: split-head transposed [b,h,dk,s] + bias -> fp16 (v,imf)
// MODE 3: batched plain * scale -> fp16 (scores / p@imf)
// MODE 4: batched merge-head [b,sq,h*dk] -> fp16 (x)
// ---------------------------------------------------------------------------
#define BM 128
#define BN 128
#define LROWH 40                       // padded row stride in halves (80 B)
#define TILE_BYTES (128 * LROWH * 2)   // 10240
#define STAGE_BYTES (2 * TILE_BYTES)   // 20480
#define GEMM_SMEM (3 * STAGE_BYTES)    // 61440

template <int MODE, int S>
__global__ void __launch_bounds__(256, 2)
tgemm(const __half* __restrict__ A, const __half* __restrict__ Bm,
      const float* __restrict__ bias, void* __restrict__ Cv,
      int M, int N, int K, long long sA, long long sB, long long sC, float scale)
{
    extern __shared__ char smc[];
    const uint32_t sbase = smem_u32(smc);
    const int tid = threadIdx.x;
    const int m0 = blockIdx.y * BM;
    const int n0 = blockIdx.x * BN;
    const int z  = blockIdx.z;

    const __half* Ab = A  + (long long)z * sA;
    const __half* Bb = Bm + (long long)z * sB;

    // loader geometry: per tile, thread handles row=tid>>1, 32B half-row
    const int lrow = tid >> 1;            // 0..127
    const int lh   = (tid & 1) * 16;      // half offset 0 / 16

    // compute geometry
    const int lane = tid & 31, wid = tid >> 5;
    const int g = lane >> 2, tg = lane & 3;
    const int wm = wid & 3, wn = wid >> 2;          // 4x2 warp grid
    const int mat  = lane >> 3;                     // ldmatrix matrix id
    const int mrow = ((mat & 1) << 3) + (lane & 7);
    const int kcol = (mat >> 1) << 3;               // 0 / 8 halves

    uint32_t offA[2], offB[4];
#pragma unroll
    for (int mt = 0; mt < 2; mt++)
        offA[mt] = (uint32_t)((wm * 32 + mt * 16 + mrow) * (LROWH * 2) + kcol * 2);
#pragma unroll
    for (int p = 0; p < 4; p++)
        offB[p] = (uint32_t)(TILE_BYTES + (wn * 64 + p * 16 + mrow) * (LROWH * 2) + kcol * 2);

    float acc[2][8][4];
#pragma unroll
    for (int mt = 0; mt < 2; mt++)
#pragma unroll
        for (int nt = 0; nt < 8; nt++)
#pragma unroll
            for (int r = 0; r < 4; r++) acc[mt][nt][r] = 0.f;

    const int T = K >> 5;

    auto issue = [&](int slot, int k0) {
        const uint32_t ab  = sbase + (uint32_t)slot * STAGE_BYTES;
        const uint32_t bb2 = ab + TILE_BYTES;
        const uint32_t so  = (uint32_t)(lrow * (LROWH * 2) + lh * 2);
        cp16(ab  + so,      Ab + (long long)(m0 + lrow) * K + k0 + lh);
        cp16(ab  + so + 16, Ab + (long long)(m0 + lrow) * K + k0 + lh + 8);
        cp16(bb2 + so,      Bb + (long long)(n0 + lrow) * K + k0 + lh);
        cp16(bb2 + so + 16, Bb + (long long)(n0 + lrow) * K + k0 + lh + 8);
        CP_COMMIT();
    };

    issue(0, 0);
    issue(1, 32);

    for (int t = 0; t < T; t++) {
        CP_WAIT1();
        __syncthreads();
        if (t + 2 < T) issue((t + 2) % 3, (t + 2) * 32);
        else CP_COMMIT();    // empty group keeps wait-count invariant

        const uint32_t stg = sbase + (uint32_t)(t % 3) * STAGE_BYTES;

#pragma unroll
        for (int kk = 0; kk < 2; kk++) {
            uint32_t a[2][4];
#pragma unroll
            for (int mt = 0; mt < 2; mt++)
                LDSM4(a[mt][0], a[mt][1], a[mt][2], a[mt][3], stg + offA[mt] + kk * 32);
            uint32_t b[8][2];
#pragma unroll
            for (int p = 0; p < 4; p++) {
                uint32_t r0, r1, r2, r3;
                LDSM4(r0, r1, r2, r3, stg + offB[p] + kk * 32);
                b[2 * p][0] = r0; b[2 * p][1] = r2;
                b[2 * p + 1][0] = r1; b[2 * p + 1][1] = r3;
            }
#pragma unroll
            for (int mt = 0; mt < 2; mt++)
#pragma unroll
                for (int nt = 0; nt < 8; nt++)
                    asm volatile(
                        "mma.sync.aligned.m16n8k16.row.col.f32.f16.f16.f32 "
                        "{%0,%1,%2,%3}, {%4,%5,%6,%7}, {%8,%9}, {%0,%1,%2,%3};"
                        : "+f"(acc[mt][nt][0]), "+f"(acc[mt][nt][1]),
                          "+f"(acc[mt][nt][2]), "+f"(acc[mt][nt][3])
                        : "r"(a[mt][0]), "r"(a[mt][1]), "r"(a[mt][2]), "r"(a[mt][3]),
                          "r"(b[nt][0]), "r"(b[nt][1]));
        }
    }

    // ---- epilogue ----
#pragma unroll
    for (int mt = 0; mt < 2; mt++) {
#pragma unroll
        for (int j = 0; j < 2; j++) {
            const int rabs = m0 + wm * 32 + mt * 16 + g + 8 * j;
#pragma unroll
            for (int nt = 0; nt < 8; nt++) {
                const int cabs = n0 + wn * 64 + nt * 8 + tg * 2;
                const float v0 = acc[mt][nt][2 * j + 0];
                const float v1 = acc[mt][nt][2 * j + 1];

                if (MODE == 0) {
                    float* C = (float*)Cv;
                    *(float2*)(C + (long long)rabs * N + cabs) =
                        make_float2(v0 + bias[cabs], v1 + bias[cabs + 1]);
                } else if (MODE == 1) {
                    __half* C = (__half*)Cv;
                    const int bb = rabs / S, s = rabs % S;
                    const int h = cabs >> 9, dk = cabs & 511;
                    *(__half2*)(C + (((long long)(bb * Hc + h) * S + s) << 9) + dk) =
                        __floats2half2_rn(v0 + bias[cabs], v1 + bias[cabs + 1]);
                } else if (MODE == 2) {
                    __half* C = (__half*)Cv;
                    const int bb = rabs / S, s = rabs % S;
                    const int h = cabs >> 9, dk = cabs & 511;
                    __half* base = C + ((long long)(bb * Hc + h) * DKc + dk) * S + s;
                    base[0]           = __float2half_rn(v0 + bias[cabs]);
                    base[(long long)S] = __float2half_rn(v1 + bias[cabs + 1]);
                } else if (MODE == 3) {
                    __half* C = (__half*)Cv;
                    *(__half2*)(C + (long long)z * sC + (long long)rabs * N + cabs) =
                        __floats2half2_rn(v0 * scale, v1 * scale);
                } else {  // MODE 4
                    __half* C = (__half*)Cv;
                    const int bb = z >> 3, h = z & 7;
                    *(__half2*)(C + (long long)(bb * SQc + rabs) * DMc + h * DKc + cabs) =
                        __floats2half2_rn(v0, v1);
                }
            }
        }
    }
}

// ---------------------------------------------------------------------------
// fp32 -> fp16 conversion (inputs / weights, once)
// ---------------------------------------------------------------------------
__global__ void cvt_h(const float4* __restrict__ in, __half2* __restrict__ out, int n4)
{
    int i = blockIdx.x * blockDim.x + threadIdx.x;
    if (i < n4) {
        float4 v = in[i];
        out[2 * i]     = __floats2half2_rn(v.x, v.y);
        out[2 * i + 1] = __floats2half2_rn(v.z, v.w);
    }
}

// ---------------------------------------------------------------------------
// Row softmax, 512 halves/row, one warp per row, fp32 internals.
// ---------------------------------------------------------------------------
__global__ void softmax512h(__half2* __restrict__ data, int nrows)
{
    const int warp = (blockIdx.x * blockDim.x + threadIdx.x) >> 5;
    const int lane = threadIdx.x & 31;
    if (warp >= nrows) return;
    __half2* row = data + (long long)warp * 256;

    float2 v[8];
    float mx = -3.4e38f;
#pragma unroll
    for (int i = 0; i < 8; i++) {
        v[i] = __half22float2(row[lane + i * 32]);
        mx = fmaxf(mx, fmaxf(v[i].x, v[i].y));
    }
#pragma unroll
    for (int o = 16; o > 0; o >>= 1) mx = fmaxf(mx, __shfl_xor_sync(0xffffffffu, mx, o));
    float sum = 0.f;
#pragma unroll
    for (int i = 0; i < 8; i++) {
        v[i].x = __expf(v[i].x - mx);
        v[i].y = __expf(v[i].y - mx);
        sum += v[i].x + v[i].y;
    }
#pragma unroll
    for (int o = 16; o > 0; o >>= 1) sum += __shfl_xor_sync(0xffffffffu, sum, o);
    const float inv = 1.0f / sum;
#pragma unroll
    for (int i = 0; i < 8; i++)
        row[lane + i * 32] = __floats2half2_rn(v[i].x * inv, v[i].y * inv);
}

// ---------------------------------------------------------------------------
// Launch
// ---------------------------------------------------------------------------
extern "C" void kernel_launch(void* const* d_in, const int* in_sizes, int n_in,
                              void* d_out, int out_size)
{
    const float* query = (const float*)d_in[0];
    const float* key   = (const float*)d_in[1];
    const float* value = (const float*)d_in[2];
    const float* imfe  = (const float*)d_in[3];
    const float* b0 = (const float*)d_in[5];
    const float* b1 = (const float*)d_in[7];
    const float* b2 = (const float*)d_in[9];
    const float* W3 = (const float*)d_in[10]; const float* b3 = (const float*)d_in[11];
    const float* W0 = (const float*)d_in[4];
    const float* W1 = (const float*)d_in[6];
    const float* W2 = (const float*)d_in[8];
    float* out = (float*)d_out;

    __half *qh, *kh, *vh, *ih, *w0h, *w1h, *w2h, *w3h;
    __half *q, *kp, *vt, *imft, *sc, *tt, *x;
    cudaGetSymbolAddress((void**)&qh, g_qh);
    cudaGetSymbolAddress((void**)&kh, g_kh);
    cudaGetSymbolAddress((void**)&vh, g_vh);
    cudaGetSymbolAddress((void**)&ih, g_ih);
    cudaGetSymbolAddress((void**)&w0h, g_w0h);
    cudaGetSymbolAddress((void**)&w1h, g_w1h);
    cudaGetSymbolAddress((void**)&w2h, g_w2h);
    cudaGetSymbolAddress((void**)&w3h, g_w3h);
    cudaGetSymbolAddress((void**)&q,    g_q);
    cudaGetSymbolAddress((void**)&kp,   g_kp);
    cudaGetSymbolAddress((void**)&vt,   g_vt);
    cudaGetSymbolAddress((void**)&imft, g_imft);
    cudaGetSymbolAddress((void**)&sc,   g_sc);
    cudaGetSymbolAddress((void**)&tt,   g_t);
    cudaGetSymbolAddress((void**)&x,    g_x);

    cudaFuncSetAttribute(tgemm<0, 0>,   cudaFuncAttributeMaxDynamicSharedMemorySize, GEMM_SMEM);
    cudaFuncSetAttribute(tgemm<1, SQc>, cudaFuncAttributeMaxDynamicSharedMemorySize, GEMM_SMEM);
    cudaFuncSetAttribute(tgemm<1, SKc>, cudaFuncAttributeMaxDynamicSharedMemorySize, GEMM_SMEM);
    cudaFuncSetAttribute(tgemm<2, SKc>, cudaFuncAttributeMaxDynamicSharedMemorySize, GEMM_SMEM);
    cudaFuncSetAttribute(tgemm<3, 0>,   cudaFuncAttributeMaxDynamicSharedMemorySize, GEMM_SMEM);
    cudaFuncSetAttribute(tgemm<4, 0>,   cudaFuncAttributeMaxDynamicSharedMemorySize, GEMM_SMEM);

    const dim3 blk(256);
    const float scl = 1.0f / sqrtf((float)DKc);

    // ---- fp32 -> fp16 (inputs + weights) ----
    const int NQ = Bc * SQc * DMc, NK = Bc * SKc * DMc, NW = DMc * DMc;
    cvt_h<<<(NQ / 4 + 255) / 256, 256>>>((const float4*)query, (__half2*)qh, NQ / 4);
    cvt_h<<<(NK / 4 + 255) / 256, 256>>>((const float4*)key,   (__half2*)kh, NK / 4);
    cvt_h<<<(NK / 4 + 255) / 256, 256>>>((const float4*)value, (__half2*)vh, NK / 4);
    cvt_h<<<(NK / 4 + 255) / 256, 256>>>((const float4*)imfe,  (__half2*)ih, NK / 4);
    cvt_h<<<(NW / 4 + 255) / 256, 256>>>((const float4*)W0, (__half2*)w0h, NW / 4);
    cvt_h<<<(NW / 4 + 255) / 256, 256>>>((const float4*)W1, (__half2*)w1h, NW / 4);
    cvt_h<<<(NW / 4 + 255) / 256, 256>>>((const float4*)W2, (__half2*)w2h, NW / 4);
    cvt_h<<<(NW / 4 + 255) / 256, 256>>>((const float4*)W3, (__half2*)w3h, NW / 4);

    // ---- projections ----
    tgemm<1, SQc><<<dim3(DMc / BN, (Bc * SQc) / BM, 1), blk, GEMM_SMEM>>>(
        qh, w0h, b0, q, Bc * SQc, DMc, DMc, 0, 0, 0, 1.f);
    tgemm<1, SKc><<<dim3(DMc / BN, (Bc * SKc) / BM, 1), blk, GEMM_SMEM>>>(
        kh, w1h, b1, kp, Bc * SKc, DMc, DMc, 0, 0, 0, 1.f);
    tgemm<2, SKc><<<dim3(DMc / BN, (Bc * SKc) / BM, 1), blk, GEMM_SMEM>>>(
        vh, w2h, b2, vt, Bc * SKc, DMc, DMc, 0, 0, 0, 1.f);
    tgemm<2, SKc><<<dim3(DMc / BN, (Bc * SKc) / BM, 1), blk, GEMM_SMEM>>>(
        ih, w3h, b3, imft, Bc * SKc, DMc, DMc, 0, 0, 0, 1.f);

    // ---- scores = q @ k^T * scl -> softmax -> p_attn ----
    tgemm<3, 0><<<dim3(SKc / BN, SQc / BM, Bc * Hc), blk, GEMM_SMEM>>>(
        q, kp, nullptr, sc, SQc, SKc, DKc,
        (long long)SQc * DKc, (long long)SKc * DKc, (long long)SQc * SKc, scl);
    softmax512h<<<(Bc * Hc * SQc) / 8, 256>>>((__half2*)sc, Bc * Hc * SQc);

    // ---- t = p_attn @ imf -> softmax -> im_attn ----
    tgemm<3, 0><<<dim3(DKc / BN, SQc / BM, Bc * Hc), blk, GEMM_SMEM>>>(
        sc, imft, nullptr, tt, SQc, DKc, SKc,
        (long long)SQc * SKc, (long long)DKc * SKc, (long long)SQc * DKc, 1.f);
    softmax512h<<<(Bc * Hc * SQc) / 8, 256>>>((__half2*)tt, Bc * Hc * SQc);

    // ---- x = im_attn @ v (merge heads) ----
    tgemm<4, 0><<<dim3(DKc / BN, SQc / BM, Bc * Hc), blk, GEMM_SMEM>>>(
        tt, vt, nullptr, x, SQc, DKc, DKc,
        (long long)SQc * DKc, (long long)DKc * SKc, 0, 1.f);

    // ---- out = x @ W3^T + b3 (fp32 out) ----
    tgemm<0, 0><<<dim3(DMc / BN, (Bc * SQc) / BM, 1), blk, GEMM_SMEM>>>(
        x, w3h, b3, out, Bc * SQc, DMc, DMc, 0, 0, 0, 1.f);
}